// round 3
// baseline (speedup 1.0000x reference)
#include <cuda_runtime.h>
#include <math.h>

#define DTF       1e-4f
#define TSTEPS    4000000
#define SEG       8
#define TPB       256
#define STEPS_PER_CTA (SEG*TPB)                                /* 2048 */
#define NCTA      ((TSTEPS + STEPS_PER_CTA - 1)/STEPS_PER_CTA) /* 1954 */

// smem geometry (float4 units)
#define IN_ROW    7           /* 6 payload float4 + 1 pad (24 floats/seg) */
#define OUT_ROW   5           /* 4 payload float4 + 1 pad (16 floats/seg) */
#define WARP_IN   (32*IN_ROW)   /* 224 f4 = 3584 B */
#define WARP_OUT  (32*OUT_ROW)  /* 160 f4 = 2560 B */
#define DYN_SMEM  (8*(WARP_IN+WARP_OUT)*16)  /* 49152 B */

struct SimConsts {
    float t00,t01,t10,t11;     // Trans
    float xi00,xi01,xi10,xi11; // XiCov
    float c00,c01,c10,c11;     // Cout
    float p0dt, p1, cA, sA;    // forcing scale, freq, per-step rotation
    float x00, x01;            // initial state
    float Mpow[14][4];         // Mpow[r] = (M^SEG)^(2^r); Mpow[8]=T_c, Mpow[13]=T_c^32
};
__device__ SimConsts gC;
__device__ unsigned g_ticket;
__device__ int   g_flag[NCTA];   // 0=invalid, 1=aggregate, 2=inclusive
__device__ float g_agg[NCTA*2];
__device__ float g_inc[NCTA*2];

__device__ __forceinline__ void mat2mul(const float* a, const float* b, float* o) {
    o[0]=fmaf(a[0],b[0],a[1]*b[2]); o[1]=fmaf(a[0],b[1],a[1]*b[3]);
    o[2]=fmaf(a[2],b[0],a[3]*b[2]); o[3]=fmaf(a[2],b[1],a[3]*b[3]);
}

// ---------------------------------------------------------------- setup ----
__global__ void k_setup(const float* __restrict__ A, const float* __restrict__ B,
                        const float* __restrict__ E, const float* __restrict__ cov,
                        const float* __restrict__ tp, const float* __restrict__ ini)
{
    // zero lookback state (every replay)
    for (int i = blockIdx.x*blockDim.x + threadIdx.x; i < NCTA; i += gridDim.x*blockDim.x)
        g_flag[i] = 0;
    if (blockIdx.x==0 && threadIdx.x==0) {
        g_ticket = 0u;
        float a0=A[0],a1=A[1],a2=A[2],a3=A[3];
        float b0=B[0],b1=B[1],b2=B[2],b3=B[3];
        float e0=E[0],e1=E[1],e2=E[2],e3=E[3];
        float v0=cov[0],v1=cov[1],v2=cov[2],v3=cov[3];
        float s2 = sqrtf(2.0f);
        float cb0=fmaf(v0,b0,v1*b2), cb1=fmaf(v0,b1,v1*b3);
        float cb2=fmaf(v2,b0,v3*b2), cb3=fmaf(v2,b1,v3*b3);
        float xi0=(e0-cb0)/s2, xi1=(e1-cb1)/s2, xi2=(e2-cb2)/s2, xi3=(e3-cb3)/s2;
        float n0=-s2*b0, n1=-s2*b2, n2=-s2*b1, n3=-s2*b3;
        float xc0=fmaf(xi0,n0,xi1*n2), xc1=fmaf(xi0,n1,xi1*n3);
        float xc2=fmaf(xi2,n0,xi3*n2), xc3=fmaf(xi2,n1,xi3*n3);
        float tr[4] = { 1.0f + (a0-xc0)*DTF, (a1-xc1)*DTF,
                        (a2-xc2)*DTF, 1.0f + (a3-xc3)*DTF };
        gC.t00=tr[0]; gC.t01=tr[1]; gC.t10=tr[2]; gC.t11=tr[3];
        gC.xi00=xi0; gC.xi01=xi1; gC.xi10=xi2; gC.xi11=xi3;
        gC.c00=n0*DTF; gC.c01=n1*DTF; gC.c10=n2*DTF; gC.c11=n3*DTF;
        gC.p0dt = tp[0]*DTF;
        gC.p1   = tp[1];
        double pd = (double)tp[1] * 1e-4;
        gC.cA = (float)cos(pd); gC.sA = (float)sin(pd);
        gC.x00 = ini[0]; gC.x01 = ini[1];
        float P[4]={1.f,0.f,0.f,1.f}, Q[4];
        for (int k=0;k<SEG;k++){ mat2mul(tr,P,Q); P[0]=Q[0];P[1]=Q[1];P[2]=Q[2];P[3]=Q[3]; }
        for (int i=0;i<4;i++) gC.Mpow[0][i]=P[i];
        for (int r=1;r<14;r++) mat2mul(gC.Mpow[r-1], gC.Mpow[r-1], gC.Mpow[r]);
    }
}

// One simulated step: update state (x0,x1) with forcing rotation (cc,ss).
#define UPSTATE(d0,d1) do{                                            \
    float a0_ = fmaf(xi01,(d1),cc);  a0_ = fmaf(xi00,(d0),a0_);        \
    float a1_ = xi11*(d1);           a1_ = fmaf(xi10,(d0),a1_);        \
    float nx0_ = fmaf(t01,x1,a0_);   nx0_ = fmaf(t00,x0,nx0_);         \
    float nx1_ = fmaf(t11,x1,a1_);   nx1_ = fmaf(t10,x0,nx1_);         \
    x0=nx0_; x1=nx1_;                                                  \
    float nc_ = fmaf(cc,cA,-(ss*sA)); ss = fmaf(ss,cA,cc*sA); cc=nc_;  \
} while(0)

#define OUTPAIR(o0,o1) do{ (o0)=fmaf(c00,x0,c01*x1); (o1)=fmaf(c10,x0,c11*x1); }while(0)

// ----------------------------------------------------------------- main ----
__global__ void __launch_bounds__(TPB) k_scan(const float* __restrict__ in,
                                              float* __restrict__ out)
{
    extern __shared__ float4 s4[];
    __shared__ float sa[TPB], sb[TPB];
    __shared__ float sE0, sE1;
    __shared__ int   s_tile;

    const int tid = threadIdx.x;
    const int lane = tid & 31, wid = tid >> 5;
    if (tid==0) s_tile = (int)atomicAdd(&g_ticket, 1u);
    __syncthreads();
    const int tile = s_tile;

    const float t00=gC.t00,t01=gC.t01,t10=gC.t10,t11=gC.t11;
    const float xi00=gC.xi00,xi01=gC.xi01,xi10=gC.xi10,xi11=gC.xi11;
    const float c00=gC.c00,c01=gC.c01,c10=gC.c10,c11=gC.c11;
    const float cA=gC.cA, sA=gC.sA, p0dt=gC.p0dt, p1=gC.p1;

    const int warpStepBase = tile*STEPS_PER_CTA + wid*32*SEG;
    float4* sin4  = s4 + wid*WARP_IN;
    float4* sout4 = s4 + 8*WARP_IN + wid*WARP_OUT;
    const bool full = (warpStepBase + 32*SEG <= TSTEPS);

    // ---- stage input + local segment scan (offset from zero state) ----
    float x0=0.f, x1=0.f;
    float cc=0.f, ss=0.f;
    if (full) {
        const float4* p4 = (const float4*)in + (size_t)warpStepBase*3/4;
        #pragma unroll
        for (int i=0;i<6;i++){
            int q = lane + 32*i;            // 0..191 float4s
            float4 v = p4[q];
            int to = q/6, c = q - to*6;
            sin4[to*IN_ROW + c] = v;
        }
        __syncwarp();
        const float4* row = sin4 + lane*IN_ROW;
        #pragma unroll
        for (int j=0;j<2;j++){
            float4 a=row[3*j], b=row[3*j+1], c=row[3*j+2];
            if (j==0){ float sv,cv; sincosf(p1*a.x,&sv,&cv); cc=p0dt*cv; ss=p0dt*sv; }
            UPSTATE(a.y,a.z);
            UPSTATE(b.x,b.y);
            UPSTATE(b.w,c.x);
            UPSTATE(c.z,c.w);
        }
        x0 -= 0.f; // keep
        // reset state to offset: we want pure offset, so subtract entry effect:
        // entry was 0, so (x0,x1) IS the offset. Save rotation restart for replay.
    } else {
        const int s0 = (tile*TPB + tid)*SEG;
        if (s0 < TSTEPS) {
            const float* p = in + (size_t)s0*3;
            float sv,cv; sincosf(p1*p[0],&sv,&cv);
            cc=p0dt*cv; ss=p0dt*sv;
            #pragma unroll
            for (int k=0;k<SEG;k++){ float d0=p[k*3+1], d1=p[k*3+2]; UPSTATE(d0,d1); }
        }
    }

    // ---- CTA Kogge-Stone over per-thread affine offsets ----
    float v0=x0, v1=x1;
    sa[tid]=v0; sb[tid]=v1;
    __syncthreads();
    #pragma unroll
    for (int r=0;r<8;r++){
        int off = 1<<r;
        float u0=0.f, u1=0.f;
        if (tid>=off){ u0=sa[tid-off]; u1=sb[tid-off]; }
        __syncthreads();
        float P0=gC.Mpow[r][0],P1=gC.Mpow[r][1],P2=gC.Mpow[r][2],P3=gC.Mpow[r][3];
        v0 = fmaf(P0,u0,fmaf(P1,u1,v0));
        v1 = fmaf(P2,u0,fmaf(P3,u1,v1));
        sa[tid]=v0; sb[tid]=v1;
        __syncthreads();
    }
    // publish CTA aggregate ASAP (tile 0 publishes inclusive below instead)
    if (tid==TPB-1 && tile>0 && tile<NCTA-1){
        g_agg[2*tile]=v0; g_agg[2*tile+1]=v1;
        __threadfence();
        atomicExch(&g_flag[tile], 1);
    }

    // ---- warp 0: decoupled lookback -> tile entry state E ----
    if (wid==0){
        float acc0=0.f, acc1=0.f;
        if (tile==0){
            acc0=gC.x00; acc1=gC.x01;
        } else {
            // per-lane Pk = T_c^lane
            float Pk[4]={1.f,0.f,0.f,1.f};
            #pragma unroll
            for (int r=0;r<5;r++) if ((lane>>r)&1){
                float Q[4]; mat2mul(gC.Mpow[8+r],Pk,Q);
                Pk[0]=Q[0];Pk[1]=Q[1];Pk[2]=Q[2];Pk[3]=Q[3];
            }
            float F[4]={1.f,0.f,0.f,1.f};
            int base = tile-1;
            for(;;){
                int j = base - lane;
                bool valid = (j>=0);
                int f;
                do {
                    f = valid ? ((volatile int*)g_flag)[j] : 1;
                } while (__any_sync(0xffffffffu, f==0));
                __threadfence();
                float w0=0.f, w1=0.f;
                unsigned m;
                {
                    float vv0=0.f, vv1=0.f;
                    if (valid){
                        const volatile float* src = (f==2) ? (volatile float*)g_inc
                                                           : (volatile float*)g_agg;
                        vv0 = src[2*j]; vv1 = src[2*j+1];
                    }
                    m = __ballot_sync(0xffffffffu, valid && f==2);
                    int cut = m ? (__ffs(m)-1) : 32;
                    if (valid && lane<=cut){
                        w0 = fmaf(Pk[0],vv0,Pk[1]*vv1);
                        w1 = fmaf(Pk[2],vv0,Pk[3]*vv1);
                    }
                }
                #pragma unroll
                for (int o=16;o;o>>=1){
                    w0 += __shfl_down_sync(0xffffffffu,w0,o);
                    w1 += __shfl_down_sync(0xffffffffu,w1,o);
                }
                if (lane==0){
                    acc0 = fmaf(F[0],w0,fmaf(F[1],w1,acc0));
                    acc1 = fmaf(F[2],w0,fmaf(F[3],w1,acc1));
                }
                if (m) break;
                float Q[4]; mat2mul(F, gC.Mpow[13], Q);
                F[0]=Q[0];F[1]=Q[1];F[2]=Q[2];F[3]=Q[3];
                base -= 32;
            }
        }
        if (lane==0){
            sE0=acc0; sE1=acc1;
            if (tile < NCTA-1){
                float a0=sa[TPB-1], a1=sb[TPB-1];
                float i0 = fmaf(gC.Mpow[8][0],acc0, fmaf(gC.Mpow[8][1],acc1, a0));
                float i1 = fmaf(gC.Mpow[8][2],acc0, fmaf(gC.Mpow[8][3],acc1, a1));
                g_inc[2*tile]=i0; g_inc[2*tile+1]=i1;
                __threadfence();
                atomicExch(&g_flag[tile], 2);
            }
        }
    }
    __syncthreads();
    const float E0=sE0, E1=sE1;

    // ---- per-thread entry = (M^SEG)^tid * E + local exclusive prefix ----
    float X0=E0, X1=E1;
    #pragma unroll
    for (int r=0;r<8;r++) if ((tid>>r)&1){
        float P0=gC.Mpow[r][0],P1=gC.Mpow[r][1],P2=gC.Mpow[r][2],P3=gC.Mpow[r][3];
        float n0=fmaf(P0,X0,P1*X1), n1=fmaf(P2,X0,P3*X1);
        X0=n0; X1=n1;
    }
    x0 = X0 + (tid ? sa[tid-1] : 0.f);
    x1 = X1 + (tid ? sb[tid-1] : 0.f);

    // ---- replay with outputs ----
    if (full) {
        const float4* row  = sin4 + lane*IN_ROW;
        float4*       orow = sout4 + lane*OUT_ROW;
        #pragma unroll
        for (int j=0;j<2;j++){
            float4 a=row[3*j], b=row[3*j+1], c=row[3*j+2];
            if (j==0){ float sv,cv; sincosf(p1*a.x,&sv,&cv); cc=p0dt*cv; ss=p0dt*sv; }
            float4 O0, O1;
            OUTPAIR(O0.x,O0.y); UPSTATE(a.y,a.z);
            OUTPAIR(O0.z,O0.w); UPSTATE(b.x,b.y);
            OUTPAIR(O1.x,O1.y); UPSTATE(b.w,c.x);
            OUTPAIR(O1.z,O1.w); UPSTATE(c.z,c.w);
            orow[2*j]   = O0;
            orow[2*j+1] = O1;
        }
        __syncwarp();
        float4* q4 = (float4*)out + (size_t)warpStepBase/2;
        #pragma unroll
        for (int i=0;i<4;i++){
            int q = lane + 32*i;            // 0..127
            int to = q>>2, c = q&3;
            q4[q] = sout4[to*OUT_ROW + c];
        }
    } else {
        const int s0 = (tile*TPB + tid)*SEG;
        if (s0 < TSTEPS) {
            const float* p = in + (size_t)s0*3;
            float sv,cv; sincosf(p1*p[0],&sv,&cv);
            cc=p0dt*cv; ss=p0dt*sv;
            #pragma unroll
            for (int k=0;k<SEG;k++){
                float d0=p[k*3+1], d1=p[k*3+2];
                out[(size_t)(s0+k)*2]   = fmaf(c00,x0,c01*x1);
                out[(size_t)(s0+k)*2+1] = fmaf(c10,x0,c11*x1);
                UPSTATE(d0,d1);
            }
        }
    }
}

// --------------------------------------------------------------- launch ----
extern "C" void kernel_launch(void* const* d_in, const int* in_sizes, int n_in,
                              void* d_out, int out_size)
{
    const float* in  = (const float*)d_in[0];
    const float* A   = (const float*)d_in[1];
    const float* B   = (const float*)d_in[2];
    // d_in[3] = D (unused by the reference)
    const float* E   = (const float*)d_in[4];
    const float* cov = (const float*)d_in[5];
    const float* tp  = (const float*)d_in[6];
    const float* ini = (const float*)d_in[7];
    float* out = (float*)d_out;

    cudaFuncSetAttribute(k_scan, cudaFuncAttributeMaxDynamicSharedMemorySize, DYN_SMEM);

    k_setup<<<8,TPB>>>(A,B,E,cov,tp,ini);
    k_scan<<<NCTA,TPB,DYN_SMEM>>>(in, out);
}

// round 5
// speedup vs baseline: 1.3716x; 1.3716x over previous
#include <cuda_runtime.h>
#include <math.h>

#define DTF       1e-4f
#define TSTEPS    4000000
#define SEG       8
#define TPB       256
#define STEPS_PER_CTA (SEG*TPB)                                /* 2048 */
#define NCTA      ((TSTEPS + STEPS_PER_CTA - 1)/STEPS_PER_CTA) /* 1954 */
#define NTH       (NCTA*TPB)

// smem geometry (float4 units)
#define IN_ROW    7            /* 6 payload f4 + 1 pad (24 floats/seg) */
#define WARP_IN   (32*IN_ROW)  /* 224 f4 = 3584 B */
#define WARP_OUT  144          /* 16 rows x (8 payload f4 + 1 pad) = 2304 B */
#define P1_SMEM   (8*WARP_IN*16)              /* 28672 B */
#define P3_SMEM   (8*(WARP_IN+WARP_OUT)*16)   /* 47104 B */

struct SimConsts {
    float t00,t01,t10,t11;     // Trans
    float xi00,xi01,xi10,xi11; // XiCov
    float c00,c01,c10,c11;     // Cout
    float p0dt, p1, cA, sA;    // forcing scale, freq, per-step rotation
    float x00, x01;            // initial state
    float Mpow[19][4];         // Mpow[r] = (M^SEG)^(2^r); [8]=M^2048, [9]=M^4096
};
__device__ SimConsts gC;
__device__ float2 g_v2[NTH];         // per-thread exclusive prefix (within CTA)
__device__ float  g_csum[NCTA*2];    // per-CTA affine offset (aggregate)
__device__ float  g_centry[NCTA*2];  // per-CTA entry state

__device__ __forceinline__ void mat2mul(const float* a, const float* b, float* o) {
    o[0]=fmaf(a[0],b[0],a[1]*b[2]); o[1]=fmaf(a[0],b[1],a[1]*b[3]);
    o[2]=fmaf(a[2],b[0],a[3]*b[2]); o[3]=fmaf(a[2],b[1],a[3]*b[3]);
}

// 32-byte evict_last load (two float4s) — policy modifier needs .v4.b64 on sm_103
__device__ __forceinline__ void ldg_el32(const float4* p, float4& a, float4& b){
    unsigned long long r0,r1,r2,r3;
    asm volatile("ld.global.L2::evict_last.v4.b64 {%0,%1,%2,%3},[%4];"
        : "=l"(r0),"=l"(r1),"=l"(r2),"=l"(r3) : "l"(p));
    a.x=__uint_as_float((unsigned)r0); a.y=__uint_as_float((unsigned)(r0>>32));
    a.z=__uint_as_float((unsigned)r1); a.w=__uint_as_float((unsigned)(r1>>32));
    b.x=__uint_as_float((unsigned)r2); b.y=__uint_as_float((unsigned)(r2>>32));
    b.z=__uint_as_float((unsigned)r3); b.w=__uint_as_float((unsigned)(r3>>32));
}

// ---------------------------------------------------------------- setup ----
__global__ void k_setup(const float* __restrict__ A, const float* __restrict__ B,
                        const float* __restrict__ E, const float* __restrict__ cov,
                        const float* __restrict__ tp, const float* __restrict__ ini)
{
    float a0=A[0],a1=A[1],a2=A[2],a3=A[3];
    float b0=B[0],b1=B[1],b2=B[2],b3=B[3];
    float e0=E[0],e1=E[1],e2=E[2],e3=E[3];
    float v0=cov[0],v1=cov[1],v2=cov[2],v3=cov[3];
    float s2 = sqrtf(2.0f);
    float cb0=fmaf(v0,b0,v1*b2), cb1=fmaf(v0,b1,v1*b3);
    float cb2=fmaf(v2,b0,v3*b2), cb3=fmaf(v2,b1,v3*b3);
    float xi0=(e0-cb0)/s2, xi1=(e1-cb1)/s2, xi2=(e2-cb2)/s2, xi3=(e3-cb3)/s2;
    float n0=-s2*b0, n1=-s2*b2, n2=-s2*b1, n3=-s2*b3;
    float xc0=fmaf(xi0,n0,xi1*n2), xc1=fmaf(xi0,n1,xi1*n3);
    float xc2=fmaf(xi2,n0,xi3*n2), xc3=fmaf(xi2,n1,xi3*n3);
    float tr[4] = { 1.0f + (a0-xc0)*DTF, (a1-xc1)*DTF,
                    (a2-xc2)*DTF, 1.0f + (a3-xc3)*DTF };
    gC.t00=tr[0]; gC.t01=tr[1]; gC.t10=tr[2]; gC.t11=tr[3];
    gC.xi00=xi0; gC.xi01=xi1; gC.xi10=xi2; gC.xi11=xi3;
    gC.c00=n0*DTF; gC.c01=n1*DTF; gC.c10=n2*DTF; gC.c11=n3*DTF;
    gC.p0dt = tp[0]*DTF;
    gC.p1   = tp[1];
    double pd = (double)tp[1] * 1e-4;
    gC.cA = (float)cos(pd); gC.sA = (float)sin(pd);
    gC.x00 = ini[0]; gC.x01 = ini[1];
    float P[4]={1.f,0.f,0.f,1.f}, Q[4];
    for (int k=0;k<SEG;k++){ mat2mul(tr,P,Q); P[0]=Q[0];P[1]=Q[1];P[2]=Q[2];P[3]=Q[3]; }
    for (int i=0;i<4;i++) gC.Mpow[0][i]=P[i];
    for (int r=1;r<19;r++) mat2mul(gC.Mpow[r-1], gC.Mpow[r-1], gC.Mpow[r]);
}

// One simulated step: update state (x0,x1) with forcing rotation (cc,ss).
#define UPSTATE(d0,d1) do{                                            \
    float a0_ = fmaf(xi01,(d1),cc);  a0_ = fmaf(xi00,(d0),a0_);        \
    float a1_ = xi11*(d1);           a1_ = fmaf(xi10,(d0),a1_);        \
    float nx0_ = fmaf(t01,x1,a0_);   nx0_ = fmaf(t00,x0,nx0_);         \
    float nx1_ = fmaf(t11,x1,a1_);   nx1_ = fmaf(t10,x0,nx1_);         \
    x0=nx0_; x1=nx1_;                                                  \
    float nc_ = fmaf(cc,cA,-(ss*sA)); ss = fmaf(ss,cA,cc*sA); cc=nc_;  \
} while(0)

#define OUTPAIR(o0,o1) do{ (o0)=fmaf(c00,x0,c01*x1); (o1)=fmaf(c10,x0,c11*x1); }while(0)

// ---------------------------------------------------------------- pass1 ----
__global__ void __launch_bounds__(TPB) k_pass1(const float* __restrict__ in)
{
    extern __shared__ float4 s4[];
    const int tid = threadIdx.x, blk = blockIdx.x;
    const int lane = tid & 31, wid = tid >> 5;
    const int gid = blk*TPB + tid;
    const float t00=gC.t00,t01=gC.t01,t10=gC.t10,t11=gC.t11;
    const float xi00=gC.xi00,xi01=gC.xi01,xi10=gC.xi10,xi11=gC.xi11;
    const float cA=gC.cA, sA=gC.sA, p0dt=gC.p0dt, p1=gC.p1;
    float x0=0.f, x1=0.f;

    const int warpStepBase = blk*STEPS_PER_CTA + wid*32*SEG;   // 256 steps/warp
    float4* sin4 = s4 + wid*WARP_IN;

    if (warpStepBase + 32*SEG <= TSTEPS) {
        const float4* p4 = (const float4*)in + (size_t)warpStepBase*3/4;
        #pragma unroll
        for (int i=0;i<3;i++){
            int ch = lane + 32*i;           // 32B chunk id, 0..95
            int q  = ch*2;                  // first float4 index (even)
            float4 va, vb;
            ldg_el32(p4+q, va, vb);
            int to = q/6, c = q - to*6;     // c in {0,2,4}; pair stays in-row
            sin4[to*IN_ROW + c]     = va;
            sin4[to*IN_ROW + c + 1] = vb;
        }
        __syncwarp();
        const float4* row = sin4 + lane*IN_ROW;
        float cc=0.f, ss=0.f;
        #pragma unroll
        for (int j=0;j<2;j++){
            float4 a=row[3*j], b=row[3*j+1], c=row[3*j+2];
            if (j==0){ float sv,cv; sincosf(p1*a.x,&sv,&cv); cc=p0dt*cv; ss=p0dt*sv; }
            UPSTATE(a.y,a.z);
            UPSTATE(b.x,b.y);
            UPSTATE(b.w,c.x);
            UPSTATE(c.z,c.w);
        }
    }
    __syncthreads();   // all warps done with staged input -> alias scan arrays

    float* sa = (float*)s4;         // 256 floats
    float* sb = sa + TPB;           // 256 floats
    float v0=x0, v1=x1;
    sa[tid]=v0; sb[tid]=v1;
    __syncthreads();
    #pragma unroll
    for (int r=0;r<8;r++){
        int off = 1<<r;
        float u0=0.f, u1=0.f;
        if (tid>=off){ u0=sa[tid-off]; u1=sb[tid-off]; }
        __syncthreads();
        float P0=gC.Mpow[r][0],P1=gC.Mpow[r][1],P2=gC.Mpow[r][2],P3=gC.Mpow[r][3];
        v0 = fmaf(P0,u0,fmaf(P1,u1,v0));
        v1 = fmaf(P2,u0,fmaf(P3,u1,v1));
        sa[tid]=v0; sb[tid]=v1;
        __syncthreads();
    }
    g_v2[gid] = make_float2(tid ? sa[tid-1] : 0.f, tid ? sb[tid-1] : 0.f);
    if (tid==TPB-1){ g_csum[2*blk]=v0; g_csum[2*blk+1]=v1; }
}

// ---------------------------------------------------------------- pass2 ----
// 1024 threads; thread g owns the tile PAIR (2g, 2g+1).
__global__ void k_pass2()
{
    const int g = threadIdx.x;
    __shared__ float sa[1024], sb[1024];
    const int u0i = 2*g, u1i = 2*g+1;
    float a00 = (u0i<NCTA)? g_csum[2*u0i]   : 0.f;
    float a01 = (u0i<NCTA)? g_csum[2*u0i+1] : 0.f;
    float a10 = (u1i<NCTA)? g_csum[2*u1i]   : 0.f;
    float a11 = (u1i<NCTA)? g_csum[2*u1i+1] : 0.f;
    const float Tc0=gC.Mpow[8][0],Tc1=gC.Mpow[8][1],Tc2=gC.Mpow[8][2],Tc3=gC.Mpow[8][3];
    float v0 = fmaf(Tc0,a00,fmaf(Tc1,a01,a10));   // pair offset
    float v1 = fmaf(Tc2,a00,fmaf(Tc3,a01,a11));
    sa[g]=v0; sb[g]=v1;
    __syncthreads();
    #pragma unroll
    for (int r=0;r<10;r++){
        int off = 1<<r;
        float w0=0.f, w1=0.f;
        if (g>=off){ w0=sa[g-off]; w1=sb[g-off]; }
        __syncthreads();
        float P0=gC.Mpow[9+r][0],P1=gC.Mpow[9+r][1],P2=gC.Mpow[9+r][2],P3=gC.Mpow[9+r][3];
        v0 = fmaf(P0,w0,fmaf(P1,w1,v0));
        v1 = fmaf(P2,w0,fmaf(P3,w1,v1));
        sa[g]=v0; sb[g]=v1;
        __syncthreads();
    }
    float e0 = g ? sa[g-1] : 0.f;
    float e1 = g ? sb[g-1] : 0.f;
    // + (M^4096)^g * x0
    float X0=gC.x00, X1=gC.x01;
    #pragma unroll
    for (int r=0;r<10;r++) if ((g>>r)&1){
        float P0=gC.Mpow[9+r][0],P1=gC.Mpow[9+r][1],P2=gC.Mpow[9+r][2],P3=gC.Mpow[9+r][3];
        float n0=fmaf(P0,X0,P1*X1), n1=fmaf(P2,X0,P3*X1);
        X0=n0; X1=n1;
    }
    float E0 = e0 + X0, E1 = e1 + X1;          // entry of tile 2g
    if (u0i<NCTA){ g_centry[2*u0i]=E0; g_centry[2*u0i+1]=E1; }
    if (u1i<NCTA){
        g_centry[2*u1i]   = fmaf(Tc0,E0,fmaf(Tc1,E1,a00));
        g_centry[2*u1i+1] = fmaf(Tc2,E0,fmaf(Tc3,E1,a01));
    }
}

// ---------------------------------------------------------------- pass3 ----
__global__ void __launch_bounds__(TPB) k_pass3(const float* __restrict__ in,
                                               float* __restrict__ out)
{
    extern __shared__ float4 s4[];
    const int tid = threadIdx.x, blk = blockIdx.x;
    const int lane = tid & 31, wid = tid >> 5;
    const int gid = blk*TPB + tid;

    const int warpStepBase = blk*STEPS_PER_CTA + wid*32*SEG;
    if (warpStepBase + 32*SEG > TSTEPS) return;   // only tile NCTA-1 warps 1..7

    const float t00=gC.t00,t01=gC.t01,t10=gC.t10,t11=gC.t11;
    const float xi00=gC.xi00,xi01=gC.xi01,xi10=gC.xi10,xi11=gC.xi11;
    const float c00=gC.c00,c01=gC.c01,c10=gC.c10,c11=gC.c11;
    const float cA=gC.cA, sA=gC.sA, p0dt=gC.p0dt, p1=gC.p1;

    float4* sin4  = s4 + wid*WARP_IN;
    float4* sout4 = s4 + 8*WARP_IN + wid*WARP_OUT;

    // ---- stage input (streaming: dead after this kernel) ----
    const float4* p4 = (const float4*)in + (size_t)warpStepBase*3/4;
    #pragma unroll
    for (int i=0;i<6;i++){
        int q = lane + 32*i;
        float4 v = __ldcs(p4+q);
        int to = q/6, c = q - to*6;
        sin4[to*IN_ROW + c] = v;
    }
    __syncwarp();

    // ---- per-thread entry = (M^SEG)^tid * tile_entry + local excl prefix ----
    float2 ex = g_v2[gid];
    float X0 = g_centry[2*blk], X1 = g_centry[2*blk+1];
    #pragma unroll
    for (int r=0;r<8;r++) if ((tid>>r)&1){
        float P0=gC.Mpow[r][0],P1=gC.Mpow[r][1],P2=gC.Mpow[r][2],P3=gC.Mpow[r][3];
        float n0=fmaf(P0,X0,P1*X1), n1=fmaf(P2,X0,P3*X1);
        X0=n0; X1=n1;
    }
    float x0 = X0 + ex.x;
    float x1 = X1 + ex.y;

    // ---- replay with outputs into conflict-free staged layout ----
    const float4* row  = sin4 + lane*IN_ROW;
    float4*       orow = sout4 + (lane>>1)*9 + (lane&1)*4;
    float cc=0.f, ss=0.f;
    #pragma unroll
    for (int j=0;j<2;j++){
        float4 a=row[3*j], b=row[3*j+1], c=row[3*j+2];
        if (j==0){ float sv,cv; sincosf(p1*a.x,&sv,&cv); cc=p0dt*cv; ss=p0dt*sv; }
        float4 O0, O1;
        OUTPAIR(O0.x,O0.y); UPSTATE(a.y,a.z);
        OUTPAIR(O0.z,O0.w); UPSTATE(b.x,b.y);
        OUTPAIR(O1.x,O1.y); UPSTATE(b.w,c.x);
        OUTPAIR(O1.z,O1.w); UPSTATE(c.z,c.w);
        orow[2*j]   = O0;
        orow[2*j+1] = O1;
    }
    __syncwarp();

    // ---- coalesced streaming store of the 2KB warp out tile ----
    float4* q4 = (float4*)out + (size_t)warpStepBase/2;
    #pragma unroll
    for (int i=0;i<4;i++){
        int q = lane + 32*i;                 // 0..127
        __stcs(q4+q, sout4[(q>>3)*9 + (q&7)]);
    }
}

// --------------------------------------------------------------- launch ----
extern "C" void kernel_launch(void* const* d_in, const int* in_sizes, int n_in,
                              void* d_out, int out_size)
{
    const float* in  = (const float*)d_in[0];
    const float* A   = (const float*)d_in[1];
    const float* B   = (const float*)d_in[2];
    // d_in[3] = D (unused by the reference)
    const float* E   = (const float*)d_in[4];
    const float* cov = (const float*)d_in[5];
    const float* tp  = (const float*)d_in[6];
    const float* ini = (const float*)d_in[7];
    float* out = (float*)d_out;

    cudaFuncSetAttribute(k_pass1, cudaFuncAttributeMaxDynamicSharedMemorySize, P1_SMEM);
    cudaFuncSetAttribute(k_pass3, cudaFuncAttributeMaxDynamicSharedMemorySize, P3_SMEM);

    k_setup<<<1,1>>>(A,B,E,cov,tp,ini);
    k_pass1<<<NCTA,TPB,P1_SMEM>>>(in);
    k_pass2<<<1,1024>>>();
    k_pass3<<<NCTA,TPB,P3_SMEM>>>(in, out);
}